// round 14
// baseline (speedup 1.0000x reference)
#include <cuda_runtime.h>
#include <cuda_fp16.h>
#include <stdint.h>
#include <math.h>

#define DIM 256
#define NGATES 46
#define NROWS 32768
#define BM 32
#define GRID 148
#define UNITS (NROWS / BM)          // 1024
#define NMY_THRESH (UNITS - 6 * GRID)   // 136: ctas < this do 7 units, else 6
#define THREADS 512

// ---- GEMM smem layout ----
#define SB_OFF 0                    // 2 x 65536 (B chunk: 512 n-rows x 128B, swizzled)
#define SA_OFF 131072               // 2 x 16384 (A unit: 32 rows x 512B, swizzled)
#define SYP_OFF 163840              // float[8][32][8] = 8192
#define SYO_OFF 172032              // float[256] = 1024
#define SMEM_TOT 173056

// Scratch (device globals — no allocation)
__device__ __half g_Xh[(size_t)NROWS * 256];   // [row][d]  fp16(x)
__device__ __half g_Wcat[512 * 512];           // [c][ vh(256) | vl(256) ],  V = 128*W

struct Cplx { float x, y; };
__device__ __forceinline__ Cplx cmul(Cplx a, Cplx b) { return {a.x*b.x - a.y*b.y, a.x*b.y + a.y*b.x}; }
__device__ __forceinline__ Cplx cadd(Cplx a, Cplx b) { return {a.x + b.x, a.y + b.y}; }

// ---------------- fused: build_U (blocks 0-31, warp-per-column) + prep_x ----------------
__global__ void prep_build_kernel(const float* __restrict__ x,
                                  const float* __restrict__ th1,
                                  const float* __restrict__ th2,
                                  const float* __restrict__ th3) {
    const int tid = threadIdx.x;
    if (blockIdx.x < 32) {
        __shared__ float2 s[8][DIM];
        __shared__ Cplx M[NGATES][4];
        const int wid = tid >> 5, l = tid & 31;
        const int col = blockIdx.x * 8 + wid;

        if (tid < NGATES) {
            int g = tid, a, r;
            if (g < 16)      { a = 0; r = g; }
            else if (g < 30) { a = 1; r = g - 16; }
            else             { a = 2; r = g - 30; }
            const float* th = (a == 0) ? th1 : ((a == 1) ? th2 : th3);
            float t1 = th[r*3 + 0], t2 = th[r*3 + 1], t3 = th[r*3 + 2];
            float cx, sx, cy, sy, cz, szv;
            sincosf(0.5f * t1, &sx, &cx);
            sincosf(0.5f * t2, &sy, &cy);
            sincosf(0.5f * t3, &szv, &cz);
            Cplx A00 = { cy*cx,  sy*sx};
            Cplx A01 = {-sy*cx, -cy*sx};
            Cplx A10 = { sy*cx, -cy*sx};
            Cplx A11 = { cy*cx, -sy*sx};
            Cplx em = {cz, -szv}, ep = {cz, szv};
            M[tid][0] = cmul(em, A00);
            M[tid][1] = cmul(em, A01);
            M[tid][2] = cmul(ep, A10);
            M[tid][3] = cmul(ep, A11);
        }
        float2* sw = s[wid];
#pragma unroll
        for (int j = 0; j < 8; j++) {
            int k = l + 32 * j;
            sw[k] = make_float2(k == col ? 1.0f : 0.0f, 0.0f);
        }
        __syncthreads();

        const int nqs[3] = {8, 7, 8};
        int g = 0;
        for (int a = 0; a < 3; a++) {
            const int nq = nqs[a];
            for (int d = 0; d < 2; d++) {
                for (int q = 0; q < nq; q++) {
                    Cplx m00 = M[g][0], m01 = M[g][1], m10 = M[g][2], m11 = M[g][3];
                    g++;
#pragma unroll
                    for (int pp = 0; pp < 4; pp++) {
                        int p = l + 32 * pp;
                        int i0 = ((p >> q) << (q + 1)) | (p & ((1 << q) - 1));
                        int i1 = i0 | (1 << q);
                        float2 a0 = sw[i0], a1 = sw[i1];
                        Cplx ca0 = {a0.x, a0.y}, ca1 = {a1.x, a1.y};
                        Cplx n0 = cadd(cmul(m00, ca0), cmul(m01, ca1));
                        Cplx n1 = cadd(cmul(m10, ca0), cmul(m11, ca1));
                        sw[i0] = make_float2(n0.x, n0.y);
                        sw[i1] = make_float2(n1.x, n1.y);
                    }
                    __syncwarp();
                }
                for (int q = 0; q < nq - 1; q++) {
#pragma unroll
                    for (int mm = 0; mm < 2; mm++) {
                        int m = l + 32 * mm;
                        int base = ((m >> q) << (q + 2)) | (m & ((1 << q) - 1));
                        int i0 = base | (1 << q);
                        int i1 = i0 | (2 << q);
                        float2 t = sw[i0]; sw[i0] = sw[i1]; sw[i1] = t;
                    }
                    __syncwarp();
                }
            }
        }
        // W[c=k][col] = Re U[k][col], W[256+k][col] = Im. Store V=128*W split hi/lo fp16.
#pragma unroll
        for (int j = 0; j < 8; j++) {
            int k = l + 32 * j;
            float vr = sw[k].x * 128.f, vi = sw[k].y * 128.f;
            __half rh = __float2half_rn(vr);
            __half rl = __float2half_rn(vr - __half2float(rh));
            __half ih = __float2half_rn(vi);
            __half il = __float2half_rn(vi - __half2float(ih));
            g_Wcat[(size_t)k * 512 + col]               = rh;
            g_Wcat[(size_t)k * 512 + 256 + col]         = rl;
            g_Wcat[(size_t)(256 + k) * 512 + col]       = ih;
            g_Wcat[(size_t)(256 + k) * 512 + 256 + col] = il;
        }
    } else {
        // ---- prep_x: 16 rows/block, 16 threads/row, 4 float4 each ----
        int row = (blockIdx.x - 32) * 16 + (tid >> 4);
        int q0 = tid & 15;
        const float4* xr = reinterpret_cast<const float4*>(x + (size_t)row * 256);
        __half2* dst = reinterpret_cast<__half2*>(&g_Xh[(size_t)row * 256]);
#pragma unroll
        for (int i = 0; i < 4; i++) {
            int q = q0 + 16 * i;
            float4 v = xr[q];
            dst[q * 2 + 0] = __floats2half2_rn(v.x, v.y);
            dst[q * 2 + 1] = __floats2half2_rn(v.z, v.w);
        }
    }
}

// ---------------- persistent GEMM + epilogue ----------------
__device__ __forceinline__ void cpa16(unsigned int d, const void* s) {
    asm volatile("cp.async.cg.shared.global [%0], [%1], 16;\n" :: "r"(d), "l"(s));
}
#define CP_COMMIT() asm volatile("cp.async.commit_group;\n" ::: "memory")
#define CP_WAIT(N)  asm volatile("cp.async.wait_group %0;\n" :: "n"(N) : "memory")

#define LDSM4(R0,R1,R2,R3,ADDR) \
    asm volatile("ldmatrix.sync.aligned.m8n8.x4.shared.b16 {%0,%1,%2,%3}, [%4];" \
        : "=r"(R0), "=r"(R1), "=r"(R2), "=r"(R3) : "r"(ADDR))

#define MMA16816(C, A, B0, B1) \
    asm volatile("mma.sync.aligned.m16n8k16.row.col.f32.f16.f16.f32 " \
        "{%0,%1,%2,%3},{%4,%5,%6,%7},{%8,%9},{%0,%1,%2,%3};" \
        : "+f"((C)[0]), "+f"((C)[1]), "+f"((C)[2]), "+f"((C)[3]) \
        : "r"((A)[0]), "r"((A)[1]), "r"((A)[2]), "r"((A)[3]), "r"(B0), "r"(B1))

// B chunk ci (0..7): 512 n-rows x 64 k halfs (128B rows), XOR-swizzled 16B units
__device__ __forceinline__ void loadB(unsigned int sb, int tid, int buf, int ci) {
    unsigned int dst = sb + SB_OFF + buf * 65536;
    const __half* src = &g_Wcat[ci * 64];
#pragma unroll
    for (int p = 0; p < 8; p++) {
        int u = tid + p * THREADS;
        int n = u >> 3, k = u & 7;
        cpa16(dst + n * 128 + (((unsigned)(k ^ (n & 7))) << 4),
              src + (size_t)n * 512 + k * 8);
    }
}
// A unit: 32 rows x 256 k halfs (512B rows), XOR-swizzled low-3 of k16
__device__ __forceinline__ void loadA(unsigned int sb, int tid, int buf, int unit) {
    unsigned int dst = sb + SA_OFF + buf * 16384;
    const __half* src = &g_Xh[(size_t)unit * 32 * 256];
#pragma unroll
    for (int p = 0; p < 2; p++) {
        int u = tid + p * THREADS;
        int r = u >> 5, k = u & 31;
        cpa16(dst + r * 512 + (((unsigned)(k ^ (r & 7))) << 4),
              src + (size_t)r * 256 + k * 8);
    }
}

__global__ __launch_bounds__(THREADS, 1)
void pqc_gemm_kernel(float* __restrict__ out) {
    extern __shared__ char smem[];
    float* ypart = reinterpret_cast<float*>(smem + SYP_OFF);  // [8 wn][32 r][8 ob]
    float* yout  = reinterpret_cast<float*>(smem + SYO_OFF);  // [32][8]

    const int tid = threadIdx.x;
    const int l = tid & 31;
    const int wid = tid >> 5;
    const int wm = wid & 1;        // 16-row group
    const int wn = wid >> 1;       // 64-col group (0..7 over N=512)
    const int cta = blockIdx.x;

    unsigned int sb;
    asm("{ .reg .u64 t; cvta.to.shared.u64 t, %1; cvt.u32.u64 %0, t; }" : "=r"(sb) : "l"(smem));

    const int nmy = (cta < NMY_THRESH) ? 7 : 6;
    const int gtot = nmy * 8;

    float acc[8][4];
#pragma unroll
    for (int nt = 0; nt < 8; nt++)
#pragma unroll
        for (int e = 0; e < 4; e++) acc[nt][e] = 0.0f;

    // prologue: group0 = {A(unit0), B chunk0}, group1 = {B chunk1}
    loadA(sb, tid, 0, cta);
    loadB(sb, tid, 0, 0);
    CP_COMMIT();
    loadB(sb, tid, 1, 1);
    CP_COMMIT();

    for (int g = 0; g < gtot; g++) {
        const int ci = g & 7;
        const int iu = g >> 3;
        if (g + 1 < gtot) { CP_WAIT(1); } else { CP_WAIT(0); }
        __syncthreads();

        unsigned int aB = sb + SA_OFF + (iu & 1) * 16384;
        unsigned int bB = sb + SB_OFF + (g & 1) * 65536;
        const int aSlice = (ci & 3) * 8;   // chunk ci pairs W k-range ci*64.. with X slice (ci&3)*64
#pragma unroll
        for (int kk = 0; kk < 64; kk += 16) {
            unsigned int a[4], b[4][4];
            {
                int r = wm * 16 + (l & 15);
                int k16 = aSlice + (kk >> 3) + (l >> 4);
                unsigned int addr = aB + r * 512 + (((unsigned)(k16 ^ (r & 7))) << 4);
                LDSM4(a[0], a[1], a[2], a[3], addr);
            }
#pragma unroll
            for (int bn = 0; bn < 4; bn++) {
                int n = wn * 64 + bn * 16 + (l & 7) + ((l >> 4) & 1) * 8;
                int k16 = (kk >> 3) + ((l >> 3) & 1);
                unsigned int addr = bB + n * 128 + (((unsigned)(k16 ^ (n & 7))) << 4);
                LDSM4(b[bn][0], b[bn][1], b[bn][2], b[bn][3], addr);
            }
#pragma unroll
            for (int nt = 0; nt < 8; nt++)
                MMA16816(acc[nt], a, b[nt >> 1][(nt & 1) * 2], b[nt >> 1][(nt & 1) * 2 + 1]);
        }
        __syncthreads();   // buffers consumed; safe to refill

        int nx = g + 2;
        if (nx < gtot) {
            if ((nx & 7) == 0) loadA(sb, tid, (nx >> 3) & 1, cta + (nx >> 3) * GRID);
            loadB(sb, tid, nx & 1, nx & 7);
            CP_COMMIT();
        }

        if (ci == 7) {
            // ---- epilogue for unit iu ----
            // col c = wn*64 + nt*8 + 2*(l&3) + e ; k = c & 255
            // k bits: b0=e(j7), b1..2=l&3(j6,j5), b3..5=nt(j4,j3,j2), b6=wn&1(j1), b7=(wn>>1)&1(j0)
            const int unit = cta + iu * GRID;
            float yp[2][8];
#pragma unroll
            for (int half = 0; half < 2; half++) {
                float s0 = 0.f, T7 = 0.f, T4 = 0.f, T3 = 0.f, T2 = 0.f;
#pragma unroll
                for (int nt = 0; nt < 8; nt++) {
                    float v0 = acc[nt][2 * half];
                    float v1 = acc[nt][2 * half + 1];
                    float p1 = v1 * v1;
                    float ps = v0 * v0 + p1;
                    s0 += ps; T7 += p1;
                    if (nt & 1) T4 += ps;
                    if (nt & 2) T3 += ps;
                    if (nt & 4) T2 += ps;
                }
                yp[half][7] = s0 - 2.f * T7;
                yp[half][4] = s0 - 2.f * T4;
                yp[half][3] = s0 - 2.f * T3;
                yp[half][2] = s0 - 2.f * T2;
                yp[half][6] = (l & 1) ? -s0 : s0;
                yp[half][5] = (l & 2) ? -s0 : s0;
                yp[half][1] = (wn & 1) ? -s0 : s0;
                yp[half][0] = (wn & 2) ? -s0 : s0;
            }
#pragma unroll
            for (int off = 1; off <= 2; off <<= 1)
#pragma unroll
                for (int half = 0; half < 2; half++)
#pragma unroll
                    for (int ob = 0; ob < 8; ob++)
                        yp[half][ob] += __shfl_xor_sync(0xffffffffu, yp[half][ob], off);

            if ((l & 3) == 0) {
#pragma unroll
                for (int half = 0; half < 2; half++) {
                    int r = wm * 16 + half * 8 + (l >> 2);
                    float* dst = &ypart[((size_t)wn * 32 + r) * 8];
#pragma unroll
                    for (int ob = 0; ob < 8; ob++) dst[ob] = yp[half][ob];
                }
            }
            __syncthreads();

            if (tid < 256) {
                int row = tid >> 3, ob = tid & 7;
                float v = 0.f;
#pragma unroll
                for (int w = 0; w < 8; w++) v += ypart[((size_t)w * 32 + row) * 8 + ob];
                yout[tid] = v;
            }
            __syncthreads();
            if (tid < 32) {
                float yv[8], n2 = 0.f;
#pragma unroll
                for (int ob = 0; ob < 8; ob++) { yv[ob] = yout[tid * 8 + ob]; n2 += yv[ob] * yv[ob]; }
                float inv = 1.0f / fmaxf(n2, 1e-30f);
#pragma unroll
                for (int ob = 0; ob < 8; ob++) yout[tid * 8 + ob] = yv[ob] * yv[ob] * inv;
            }
            __syncthreads();
            // write 32 rows x 64 float4 (only q<2 nonzero)
#pragma unroll
            for (int i = 0; i < 4; i++) {
                int idx = tid + i * THREADS;
                int rr = idx >> 6, q = idx & 63;
                float4 v = make_float4(0.f, 0.f, 0.f, 0.f);
                if (q == 0)      v = *reinterpret_cast<float4*>(&yout[rr * 8]);
                else if (q == 1) v = *reinterpret_cast<float4*>(&yout[rr * 8 + 4]);
                reinterpret_cast<float4*>(out + (size_t)(unit * 32 + rr) * 256)[q] = v;
            }
            __syncthreads();   // ypart/yout free before next unit's epilogue

#pragma unroll
            for (int nt = 0; nt < 8; nt++)
#pragma unroll
                for (int e = 0; e < 4; e++) acc[nt][e] = 0.0f;
        }
    }
}

extern "C" void kernel_launch(void* const* d_in, const int* in_sizes, int n_in,
                              void* d_out, int out_size) {
    const float* x   = (const float*)d_in[0];
    const float* th1 = (const float*)d_in[1];
    const float* th2 = (const float*)d_in[2];
    const float* th3 = (const float*)d_in[3];
    float* out = (float*)d_out;

    int nrows = in_sizes[0] / 256;   // 32768

    cudaFuncSetAttribute(pqc_gemm_kernel,
                         cudaFuncAttributeMaxDynamicSharedMemorySize, SMEM_TOT);

    prep_build_kernel<<<32 + nrows / 16, 256>>>(x, th1, th2, th3);
    pqc_gemm_kernel<<<GRID, THREADS, SMEM_TOT>>>(out);
}

// round 15
// speedup vs baseline: 1.7872x; 1.7872x over previous
#include <cuda_runtime.h>
#include <cuda_fp16.h>
#include <stdint.h>
#include <math.h>

#define DIM 256
#define NGATES 46
#define NROWS 32768
#define BM 32
#define GRID 148
#define UNITS (NROWS / BM)              // 1024
#define NMY_THRESH (UNITS - 6 * GRID)   // 136: ctas < this do 7 units, else 6
#define THREADS 512

// ---- GEMM smem layout ----
#define SB_OFF 0                    // 2 x 65536 (B chunk: 512 n-rows x 128B, swizzled)
#define SA_OFF 131072               // 2 x 16384 (A unit: 32 rows x 512B, swizzled)
#define SYP_OFF 163840              // float[8][32][8] = 8192
#define SYO_OFF 172032              // float[256] = 1024
#define SMEM_TOT 173056

// Scratch (device globals — no allocation)
__device__ __half g_Xh[(size_t)NROWS * 256];   // [row][d]  fp16(x)
__device__ __half g_Wh[512 * 256];             // [c][d]    fp16(W), c<256:Re, c>=256:Im

struct Cplx { float x, y; };
__device__ __forceinline__ Cplx cmul(Cplx a, Cplx b) { return {a.x*b.x - a.y*b.y, a.x*b.y + a.y*b.x}; }
__device__ __forceinline__ Cplx cadd(Cplx a, Cplx b) { return {a.x + b.x, a.y + b.y}; }

// ---------------- fused: build_U (blocks 0-255, block-per-column) + prep_x ----------------
__global__ void prep_build_kernel(const float* __restrict__ x,
                                  const float* __restrict__ th1,
                                  const float* __restrict__ th2,
                                  const float* __restrict__ th3) {
    const int tid = threadIdx.x;
    if (blockIdx.x < 256) {
        __shared__ float2 s[DIM];
        __shared__ Cplx M[NGATES][4];
        const int col = blockIdx.x;   // basis state d

        if (tid < NGATES) {
            int g = tid, a, r;
            if (g < 16)      { a = 0; r = g; }
            else if (g < 30) { a = 1; r = g - 16; }
            else             { a = 2; r = g - 30; }
            const float* th = (a == 0) ? th1 : ((a == 1) ? th2 : th3);
            float t1 = th[r*3 + 0], t2 = th[r*3 + 1], t3 = th[r*3 + 2];
            float cx, sx, cy, sy, cz, szv;
            sincosf(0.5f * t1, &sx, &cx);
            sincosf(0.5f * t2, &sy, &cy);
            sincosf(0.5f * t3, &szv, &cz);
            Cplx A00 = { cy*cx,  sy*sx};
            Cplx A01 = {-sy*cx, -cy*sx};
            Cplx A10 = { sy*cx, -cy*sx};
            Cplx A11 = { cy*cx, -sy*sx};
            Cplx em = {cz, -szv}, ep = {cz, szv};
            M[tid][0] = cmul(em, A00);
            M[tid][1] = cmul(em, A01);
            M[tid][2] = cmul(ep, A10);
            M[tid][3] = cmul(ep, A11);
        }
        if (tid < 128)
            for (int k = tid; k < DIM; k += 128)
                s[k] = make_float2(k == col ? 1.0f : 0.0f, 0.0f);
        __syncthreads();

        const int nqs[3] = {8, 7, 8};
        int g = 0;
        for (int a = 0; a < 3; a++) {
            const int nq = nqs[a];
            for (int d = 0; d < 2; d++) {
                for (int q = 0; q < nq; q++) {
                    if (tid < 128) {
                        Cplx m00 = M[g][0], m01 = M[g][1], m10 = M[g][2], m11 = M[g][3];
                        int p = tid;
                        int i0 = ((p >> q) << (q + 1)) | (p & ((1 << q) - 1));
                        int i1 = i0 | (1 << q);
                        float2 a0 = s[i0], a1 = s[i1];
                        Cplx ca0 = {a0.x, a0.y}, ca1 = {a1.x, a1.y};
                        Cplx n0 = cadd(cmul(m00, ca0), cmul(m01, ca1));
                        Cplx n1 = cadd(cmul(m10, ca0), cmul(m11, ca1));
                        s[i0] = make_float2(n0.x, n0.y);
                        s[i1] = make_float2(n1.x, n1.y);
                    }
                    g++;
                    __syncthreads();
                }
                for (int q = 0; q < nq - 1; q++) {
                    if (tid < 64) {
                        int m = tid;
                        int base = ((m >> q) << (q + 2)) | (m & ((1 << q) - 1));
                        int i0 = base | (1 << q);
                        int i1 = i0 | (2 << q);
                        float2 t = s[i0]; s[i0] = s[i1]; s[i1] = t;
                    }
                    __syncthreads();
                }
            }
        }
        // W[c=k][col] = Re U[k][col], W[256+k][col] = Im — plain fp16
        if (tid < 128)
            for (int k = tid; k < DIM; k += 128) {
                g_Wh[(size_t)k * 256 + col]         = __float2half_rn(s[k].x);
                g_Wh[(size_t)(256 + k) * 256 + col] = __float2half_rn(s[k].y);
            }
    } else {
        // ---- prep_x: one float4 -> 4 fp16 per thread ----
        int idx = (blockIdx.x - 256) * 256 + tid;
        int row = idx >> 6;
        int q = idx & 63;
        float4 v = reinterpret_cast<const float4*>(x)[idx];
        __half2* p = reinterpret_cast<__half2*>(&g_Xh[(size_t)row * 256 + q * 4]);
        p[0] = __floats2half2_rn(v.x, v.y);
        p[1] = __floats2half2_rn(v.z, v.w);
    }
}

// ---------------- persistent GEMM + epilogue ----------------
__device__ __forceinline__ void cpa16(unsigned int d, const void* s) {
    asm volatile("cp.async.cg.shared.global [%0], [%1], 16;\n" :: "r"(d), "l"(s));
}
#define CP_COMMIT() asm volatile("cp.async.commit_group;\n" ::: "memory")
#define CP_WAIT(N)  asm volatile("cp.async.wait_group %0;\n" :: "n"(N) : "memory")

#define LDSM4(R0,R1,R2,R3,ADDR) \
    asm volatile("ldmatrix.sync.aligned.m8n8.x4.shared.b16 {%0,%1,%2,%3}, [%4];" \
        : "=r"(R0), "=r"(R1), "=r"(R2), "=r"(R3) : "r"(ADDR))

#define MMA16816(C, A, B0, B1) \
    asm volatile("mma.sync.aligned.m16n8k16.row.col.f32.f16.f16.f32 " \
        "{%0,%1,%2,%3},{%4,%5,%6,%7},{%8,%9},{%0,%1,%2,%3};" \
        : "+f"((C)[0]), "+f"((C)[1]), "+f"((C)[2]), "+f"((C)[3]) \
        : "r"((A)[0]), "r"((A)[1]), "r"((A)[2]), "r"((A)[3]), "r"(B0), "r"(B1))

// B chunk ci (0..3): 512 n-rows x 64 k halfs (128B rows), XOR-swizzled 16B units
__device__ __forceinline__ void loadB(unsigned int sb, int tid, int buf, int ci) {
    unsigned int dst = sb + SB_OFF + buf * 65536;
    const __half* src = &g_Wh[ci * 64];
#pragma unroll
    for (int p = 0; p < 8; p++) {
        int u = tid + p * THREADS;
        int n = u >> 3, k = u & 7;
        cpa16(dst + n * 128 + (((unsigned)(k ^ (n & 7))) << 4),
              src + (size_t)n * 256 + k * 8);
    }
}
// A unit: 32 rows x 256 k halfs (512B rows), XOR-swizzled low-3 of k16
__device__ __forceinline__ void loadA(unsigned int sb, int tid, int buf, int unit) {
    unsigned int dst = sb + SA_OFF + buf * 16384;
    const __half* src = &g_Xh[(size_t)unit * 32 * 256];
#pragma unroll
    for (int p = 0; p < 2; p++) {
        int u = tid + p * THREADS;
        int r = u >> 5, k = u & 31;
        cpa16(dst + r * 512 + (((unsigned)(k ^ (r & 7))) << 4),
              src + (size_t)r * 256 + k * 8);
    }
}

__global__ __launch_bounds__(THREADS, 1)
void pqc_gemm_kernel(float* __restrict__ out) {
    extern __shared__ char smem[];
    float* ypart = reinterpret_cast<float*>(smem + SYP_OFF);  // [8 wn][32 r][8 ob]
    float* yout  = reinterpret_cast<float*>(smem + SYO_OFF);  // [32][8]

    const int tid = threadIdx.x;
    const int l = tid & 31;
    const int wid = tid >> 5;
    const int wm = wid & 1;        // 16-row group
    const int wn = wid >> 1;       // 64-col group (0..7 over N=512)
    const int cta = blockIdx.x;

    unsigned int sb;
    asm("{ .reg .u64 t; cvta.to.shared.u64 t, %1; cvt.u32.u64 %0, t; }" : "=r"(sb) : "l"(smem));

    const int nmy = (cta < NMY_THRESH) ? 7 : 6;
    const int gtot = nmy * 4;

    float acc[8][4];
#pragma unroll
    for (int nt = 0; nt < 8; nt++)
#pragma unroll
        for (int e = 0; e < 4; e++) acc[nt][e] = 0.0f;

    // prologue: group0 = {A(unit0), B chunk0}, group1 = {B chunk1}
    loadA(sb, tid, 0, cta);
    loadB(sb, tid, 0, 0);
    CP_COMMIT();
    loadB(sb, tid, 1, 1);
    CP_COMMIT();

    for (int g = 0; g < gtot; g++) {
        const int ci = g & 3;
        const int iu = g >> 2;
        if (g + 1 < gtot) { CP_WAIT(1); } else { CP_WAIT(0); }
        __syncthreads();

        unsigned int aB = sb + SA_OFF + (iu & 1) * 16384;
        unsigned int bB = sb + SB_OFF + (g & 1) * 65536;
        const int aSlice = ci * 8;   // chunk ci covers k-range [64ci, 64ci+64) for both X and W
#pragma unroll
        for (int kk = 0; kk < 64; kk += 16) {
            unsigned int a[4], b[4][4];
            {
                int r = wm * 16 + (l & 15);
                int k16 = aSlice + (kk >> 3) + (l >> 4);
                unsigned int addr = aB + r * 512 + (((unsigned)(k16 ^ (r & 7))) << 4);
                LDSM4(a[0], a[1], a[2], a[3], addr);
            }
#pragma unroll
            for (int bn = 0; bn < 4; bn++) {
                int n = wn * 64 + bn * 16 + (l & 7) + ((l >> 4) & 1) * 8;
                int k16 = (kk >> 3) + ((l >> 3) & 1);
                unsigned int addr = bB + n * 128 + (((unsigned)(k16 ^ (n & 7))) << 4);
                LDSM4(b[bn][0], b[bn][1], b[bn][2], b[bn][3], addr);
            }
#pragma unroll
            for (int nt = 0; nt < 8; nt++)
                MMA16816(acc[nt], a, b[nt >> 1][(nt & 1) * 2], b[nt >> 1][(nt & 1) * 2 + 1]);
        }
        __syncthreads();   // buffers consumed; safe to refill

        int nx = g + 2;
        if (nx < gtot) {
            if ((nx & 3) == 0) loadA(sb, tid, (nx >> 2) & 1, cta + (nx >> 2) * GRID);
            loadB(sb, tid, nx & 1, nx & 3);
            CP_COMMIT();
        }

        if (ci == 3) {
            // ---- epilogue for unit iu ----
            // col c = wn*64 + nt*8 + 2*(l&3) + e ; k = c & 255
            // k bits: b0=e(j7), b1..2=l&3(j6,j5), b3..5=nt(j4,j3,j2), b6=wn&1(j1), b7=(wn>>1)&1(j0)
            const int unit = cta + iu * GRID;
            float yp[2][8];
#pragma unroll
            for (int half = 0; half < 2; half++) {
                float s0 = 0.f, T7 = 0.f, T4 = 0.f, T3 = 0.f, T2 = 0.f;
#pragma unroll
                for (int nt = 0; nt < 8; nt++) {
                    float v0 = acc[nt][2 * half];
                    float v1 = acc[nt][2 * half + 1];
                    float p1 = v1 * v1;
                    float ps = v0 * v0 + p1;
                    s0 += ps; T7 += p1;
                    if (nt & 1) T4 += ps;
                    if (nt & 2) T3 += ps;
                    if (nt & 4) T2 += ps;
                }
                yp[half][7] = s0 - 2.f * T7;
                yp[half][4] = s0 - 2.f * T4;
                yp[half][3] = s0 - 2.f * T3;
                yp[half][2] = s0 - 2.f * T2;
                yp[half][6] = (l & 1) ? -s0 : s0;
                yp[half][5] = (l & 2) ? -s0 : s0;
                yp[half][1] = (wn & 1) ? -s0 : s0;
                yp[half][0] = (wn & 2) ? -s0 : s0;
            }
#pragma unroll
            for (int off = 1; off <= 2; off <<= 1)
#pragma unroll
                for (int half = 0; half < 2; half++)
#pragma unroll
                    for (int ob = 0; ob < 8; ob++)
                        yp[half][ob] += __shfl_xor_sync(0xffffffffu, yp[half][ob], off);

            if ((l & 3) == 0) {
#pragma unroll
                for (int half = 0; half < 2; half++) {
                    int r = wm * 16 + half * 8 + (l >> 2);
                    float* dst = &ypart[((size_t)wn * 32 + r) * 8];
#pragma unroll
                    for (int ob = 0; ob < 8; ob++) dst[ob] = yp[half][ob];
                }
            }
            __syncthreads();

            if (tid < 256) {
                int row = tid >> 3, ob = tid & 7;
                float v = 0.f;
#pragma unroll
                for (int w = 0; w < 8; w++) v += ypart[((size_t)w * 32 + row) * 8 + ob];
                yout[tid] = v;
            }
            __syncthreads();
            if (tid < 32) {
                float yv[8], n2 = 0.f;
#pragma unroll
                for (int ob = 0; ob < 8; ob++) { yv[ob] = yout[tid * 8 + ob]; n2 += yv[ob] * yv[ob]; }
                float inv = 1.0f / fmaxf(n2, 1e-30f);
#pragma unroll
                for (int ob = 0; ob < 8; ob++) yout[tid * 8 + ob] = yv[ob] * yv[ob] * inv;
            }
            __syncthreads();
            // write 32 rows x 64 float4 (only q<2 nonzero)
#pragma unroll
            for (int i = 0; i < 4; i++) {
                int idx = tid + i * THREADS;
                int rr = idx >> 6, q = idx & 63;
                float4 v = make_float4(0.f, 0.f, 0.f, 0.f);
                if (q == 0)      v = *reinterpret_cast<float4*>(&yout[rr * 8]);
                else if (q == 1) v = *reinterpret_cast<float4*>(&yout[rr * 8 + 4]);
                reinterpret_cast<float4*>(out + (size_t)(unit * 32 + rr) * 256)[q] = v;
            }
            __syncthreads();   // ypart/yout free before next unit's epilogue

#pragma unroll
            for (int nt = 0; nt < 8; nt++)
#pragma unroll
                for (int e = 0; e < 4; e++) acc[nt][e] = 0.0f;
        }
    }
}

extern "C" void kernel_launch(void* const* d_in, const int* in_sizes, int n_in,
                              void* d_out, int out_size) {
    const float* x   = (const float*)d_in[0];
    const float* th1 = (const float*)d_in[1];
    const float* th2 = (const float*)d_in[2];
    const float* th3 = (const float*)d_in[3];
    float* out = (float*)d_out;

    int nrows = in_sizes[0] / 256;   // 32768

    cudaFuncSetAttribute(pqc_gemm_kernel,
                         cudaFuncAttributeMaxDynamicSharedMemorySize, SMEM_TOT);

    prep_build_kernel<<<256 + (nrows * 64) / 256, 256>>>(x, th1, th2, th3);
    pqc_gemm_kernel<<<GRID, THREADS, SMEM_TOT>>>(out);
}